// round 1
// baseline (speedup 1.0000x reference)
#include <cuda_runtime.h>
#include <cstdint>
#include <math.h>

// multi_dRNN_with_dilations: 3 stacked dilated LSTM layers (rates 1,2,4)
// T=512, B=128, H=256, D_IN=256. Fused input projection + recurrence.
//
// Grid: 16 gate-blocks (x) x 8 batch-blocks (y) = 128 CTAs, 1 CTA/SM,
// all co-resident -> custom per-batch-block barrier across the 16 gate CTAs.

#define Hc    256
#define G4H   1024
#define BATCH 128
#define TT    512
#define WSTR  516   // smem row stride (floats) for weight tile
#define USTR  516   // smem row stride for u = [x ; h]
#define PSTR  17    // padded cols for partial-sum buffer

// persistent device state (no allocations allowed)
__device__ float    g_h[2][512 * 256];   // double-buffered hidden state (max N=512)
__device__ float    g_c[512 * 256];      // cell state (CTA-private columns)
__device__ unsigned g_bar[8];            // one barrier counter per batch-block

__device__ __forceinline__ unsigned long long fma2(unsigned long long a,
                                                   unsigned long long b,
                                                   unsigned long long c) {
    unsigned long long d;
    asm("fma.rn.f32x2 %0, %1, %2, %3;" : "=l"(d) : "l"(a), "l"(b), "l"(c));
    return d;
}

__device__ __forceinline__ float pairsum(unsigned long long v) {
    unsigned lo_, hi_;
    asm("mov.b64 {%0, %1}, %2;" : "=r"(lo_), "=r"(hi_) : "l"(v));
    return __uint_as_float(lo_) + __uint_as_float(hi_);
}

__device__ __forceinline__ void bar_arrive(unsigned* p) {
    asm volatile("red.release.gpu.global.add.u32 [%0], 1;" :: "l"(p) : "memory");
}
__device__ __forceinline__ unsigned bar_peek(unsigned* p) {
    unsigned v;
    asm volatile("ld.acquire.gpu.global.u32 %0, [%1];" : "=r"(v) : "l"(p) : "memory");
    return v;
}

__device__ __forceinline__ float sigmoidf_(float x) {
    return 1.0f / (1.0f + expf(-x));
}

extern "C" __global__ void __launch_bounds__(256, 1)
drnn_layer(const float* __restrict__ input,   // (T,128,256) for this layer
           const float* __restrict__ Wih,     // (L,1024,256)
           const float* __restrict__ Whh,     // (L,1024,256)
           const float* __restrict__ bih,     // (L,1024)
           const float* __restrict__ bhh,     // (L,1024)
           float* __restrict__ out,           // (L,512,128,256)
           int layer, int rate, int Td, int Nper, int nSub, unsigned barBase)
{
    extern __shared__ float sm[];
    float* w_s    = sm;                          // 64 x WSTR
    float* u_s    = w_s + 64 * WSTR;             // 16 x USTR
    float* part   = u_s + 16 * USTR;             // 4 x 64 x PSTR
    float* bias_s = part + 4 * 64 * PSTR;        // 64

    const int g   = blockIdx.x;   // 0..15 gate-block (h-cols [16g,16g+16))
    const int nb  = blockIdx.y;   // 0..7 batch-block
    const int tid = threadIdx.x;

    const float* WihL = Wih + (size_t)layer * G4H * Hc;
    const float* WhhL = Whh + (size_t)layer * G4H * Hc;

    // ---- load stationary weight tile: rows r = q*16 + jl -> global row q*256 + g*16 + jl
    for (int idx = tid; idx < 64 * 512; idx += 256) {
        int r = idx >> 9;
        int k = idx & 511;
        int q  = r >> 4;
        int jl = r & 15;
        int R  = q * 256 + g * 16 + jl;
        float v = (k < 256) ? WihL[(size_t)R * 256 + k]
                            : WhhL[(size_t)R * 256 + (k - 256)];
        w_s[r * WSTR + k] = v;
    }
    if (tid < 64) {
        int q = tid >> 4, jl = tid & 15;
        int R = q * 256 + g * 16 + jl;
        bias_s[tid] = bih[layer * G4H + R] + bhh[layer * G4H + R];
    }
    __syncthreads();

    // thread roles
    const int kq  = tid >> 6;      // k-split 0..3 (128 k each)
    const int wkr = tid & 63;
    const int ry  = wkr >> 2;      // 0..15 local h-col
    const int cx  = wkr & 3;       // 0..3 batch lane
    const int pjl = tid & 15;      // pointwise: local h-col
    const int pn  = tid >> 4;      // pointwise: local batch row

    unsigned* barp = &g_bar[nb];

    for (int s = 0; s < Td; ++s) {
        const float* hprev = g_h[(s + 1) & 1];   // valid only for s>0
        float* hcur = g_h[s & 1];

        for (int sub = 0; sub < nSub; ++sub) {
            const int nG0 = nb * Nper + sub * 16;

            // ---- fill u = [x_t ; h_{s-1}] for 16 dilated-batch rows
            {
                int n    = tid >> 4;
                int lane = tid & 15;
                int nG   = nG0 + n;
                int rr   = nG >> 7;          // nG / 128
                int bat  = nG & 127;
                int time = s * rate + rr;
                const float* xrow = input + ((size_t)time * BATCH + bat) * Hc;
                const float* hrow = hprev + (size_t)nG * Hc;
                float* ur = u_s + n * USTR;
                #pragma unroll
                for (int i = 0; i < 4; ++i) {
                    int k = (lane + 16 * i) * 4;         // 0..252
                    *(float4*)(ur + k) = *(const float4*)(xrow + k);
                }
                #pragma unroll
                for (int i = 0; i < 4; ++i) {
                    int k = (lane + 16 * i) * 4;
                    float4 v;
                    if (s == 0) v = make_float4(0.f, 0.f, 0.f, 0.f);
                    else        v = *(const float4*)(hrow + k);
                    *(float4*)(ur + 256 + k) = v;
                }
            }
            __syncthreads();

            // ---- microkernel: 64 gate-rows x 16 batch, K split 4-way, f32x2 FMA
            {
                unsigned long long acc[4][4];
                #pragma unroll
                for (int q = 0; q < 4; ++q)
                    #pragma unroll
                    for (int c = 0; c < 4; ++c) acc[q][c] = 0ULL;

                const int kb = kq * 128;
                const float* up0 = u_s + (cx     ) * USTR + kb;
                const float* up1 = u_s + (cx +  4) * USTR + kb;
                const float* up2 = u_s + (cx +  8) * USTR + kb;
                const float* up3 = u_s + (cx + 12) * USTR + kb;
                const float* wp0 = w_s + (ry      ) * WSTR + kb;
                const float* wp1 = w_s + (ry + 16 ) * WSTR + kb;
                const float* wp2 = w_s + (ry + 32 ) * WSTR + kb;
                const float* wp3 = w_s + (ry + 48 ) * WSTR + kb;

                #pragma unroll 4
                for (int kk = 0; kk < 128; kk += 4) {
                    ulonglong2 u0 = *(const ulonglong2*)(up0 + kk);
                    ulonglong2 u1 = *(const ulonglong2*)(up1 + kk);
                    ulonglong2 u2 = *(const ulonglong2*)(up2 + kk);
                    ulonglong2 u3 = *(const ulonglong2*)(up3 + kk);
                    ulonglong2 w0 = *(const ulonglong2*)(wp0 + kk);
                    ulonglong2 w1 = *(const ulonglong2*)(wp1 + kk);
                    ulonglong2 w2 = *(const ulonglong2*)(wp2 + kk);
                    ulonglong2 w3 = *(const ulonglong2*)(wp3 + kk);

                    acc[0][0] = fma2(w0.x, u0.x, acc[0][0]);
                    acc[0][1] = fma2(w0.x, u1.x, acc[0][1]);
                    acc[0][2] = fma2(w0.x, u2.x, acc[0][2]);
                    acc[0][3] = fma2(w0.x, u3.x, acc[0][3]);
                    acc[1][0] = fma2(w1.x, u0.x, acc[1][0]);
                    acc[1][1] = fma2(w1.x, u1.x, acc[1][1]);
                    acc[1][2] = fma2(w1.x, u2.x, acc[1][2]);
                    acc[1][3] = fma2(w1.x, u3.x, acc[1][3]);
                    acc[2][0] = fma2(w2.x, u0.x, acc[2][0]);
                    acc[2][1] = fma2(w2.x, u1.x, acc[2][1]);
                    acc[2][2] = fma2(w2.x, u2.x, acc[2][2]);
                    acc[2][3] = fma2(w2.x, u3.x, acc[2][3]);
                    acc[3][0] = fma2(w3.x, u0.x, acc[3][0]);
                    acc[3][1] = fma2(w3.x, u1.x, acc[3][1]);
                    acc[3][2] = fma2(w3.x, u2.x, acc[3][2]);
                    acc[3][3] = fma2(w3.x, u3.x, acc[3][3]);

                    acc[0][0] = fma2(w0.y, u0.y, acc[0][0]);
                    acc[0][1] = fma2(w0.y, u1.y, acc[0][1]);
                    acc[0][2] = fma2(w0.y, u2.y, acc[0][2]);
                    acc[0][3] = fma2(w0.y, u3.y, acc[0][3]);
                    acc[1][0] = fma2(w1.y, u0.y, acc[1][0]);
                    acc[1][1] = fma2(w1.y, u1.y, acc[1][1]);
                    acc[1][2] = fma2(w1.y, u2.y, acc[1][2]);
                    acc[1][3] = fma2(w1.y, u3.y, acc[1][3]);
                    acc[2][0] = fma2(w2.y, u0.y, acc[2][0]);
                    acc[2][1] = fma2(w2.y, u1.y, acc[2][1]);
                    acc[2][2] = fma2(w2.y, u2.y, acc[2][2]);
                    acc[2][3] = fma2(w2.y, u3.y, acc[2][3]);
                    acc[3][0] = fma2(w3.y, u0.y, acc[3][0]);
                    acc[3][1] = fma2(w3.y, u1.y, acc[3][1]);
                    acc[3][2] = fma2(w3.y, u2.y, acc[3][2]);
                    acc[3][3] = fma2(w3.y, u3.y, acc[3][3]);
                }

                #pragma unroll
                for (int q = 0; q < 4; ++q)
                    #pragma unroll
                    for (int c = 0; c < 4; ++c)
                        part[(kq * 64 + q * 16 + ry) * PSTR + (cx + 4 * c)] =
                            pairsum(acc[q][c]);
            }
            __syncthreads();

            // ---- pointwise LSTM update: one (n, jl) per thread
            {
                int n  = pn;
                int jl = pjl;
                int nG = nG0 + n;
                float gv[4];
                #pragma unroll
                for (int q = 0; q < 4; ++q) {
                    float v = bias_s[q * 16 + jl];
                    #pragma unroll
                    for (int sp = 0; sp < 4; ++sp)
                        v += part[(sp * 64 + q * 16 + jl) * PSTR + n];
                    gv[q] = v;
                }
                float ig = sigmoidf_(gv[0]);
                float fg = sigmoidf_(gv[1]);
                float gg = tanhf(gv[2]);
                float og = sigmoidf_(gv[3]);

                int   jcol = g * 16 + jl;
                size_t sidx = (size_t)nG * Hc + jcol;
                float cold = (s == 0) ? 0.f : g_c[sidx];
                float cnew = fg * cold + ig * gg;
                float hnew = og * tanhf(cnew);
                g_c[sidx]  = cnew;
                hcur[sidx] = hnew;

                int rr   = nG >> 7;
                int bat  = nG & 127;
                int time = s * rate + rr;
                out[(((size_t)layer * TT + time) * BATCH + bat) * Hc + jcol] = hnew;
            }
            __syncthreads();   // u_s / part reused by next sub-tile
        }

        // ---- barrier across the 16 gate-CTAs of this batch-block
        __threadfence();
        __syncthreads();
        if (tid == 0) {
            bar_arrive(barp);
            unsigned target = barBase + 16u * (unsigned)(s + 1);
            while (bar_peek(barp) < target) { }
        }
        __syncthreads();
    }
}

extern "C" void kernel_launch(void* const* d_in, const int* in_sizes, int n_in,
                              void* d_out, int out_size)
{
    const float* x   = (const float*)d_in[0];
    const float* Wih = (const float*)d_in[1];
    const float* Whh = (const float*)d_in[2];
    const float* bih = (const float*)d_in[3];
    const float* bhh = (const float*)d_in[4];
    float* out = (float*)d_out;

    const size_t smem = (size_t)(64 * WSTR + 16 * USTR + 4 * 64 * PSTR + 64) * sizeof(float);
    cudaFuncSetAttribute(drnn_layer, cudaFuncAttributeMaxDynamicSharedMemorySize, (int)smem);

    void* barp = nullptr;
    cudaGetSymbolAddress(&barp, g_bar);
    cudaMemsetAsync(barp, 0, 8 * sizeof(unsigned), 0);

    dim3 grid(16, 8);
    const size_t layer_elems = (size_t)TT * BATCH * Hc;

    // layer 0: rate 1, Td 512, N=128 (Nper 16, 1 sub-tile), barBase 0
    drnn_layer<<<grid, 256, smem>>>(x, Wih, Whh, bih, bhh, out,
                                    0, 1, 512, 16, 1, 0u);
    // layer 1: rate 2, Td 256, N=256 (Nper 32, 2 sub-tiles), base = 16*512
    drnn_layer<<<grid, 256, smem>>>(out, Wih, Whh, bih, bhh, out,
                                    1, 2, 256, 32, 2, 16u * 512u);
    // layer 2: rate 4, Td 128, N=512 (Nper 64, 4 sub-tiles), base = 16*(512+256)
    drnn_layer<<<grid, 256, smem>>>(out + layer_elems, Wih, Whh, bih, bhh, out,
                                    2, 4, 128, 64, 4, 16u * 768u);
}